// round 17
// baseline (speedup 1.0000x reference)
#include <cuda_runtime.h>
#include <cstdint>

// Scratch for v1[8, 1024] — __device__ global (no allocations allowed).
__device__ float g_v1[8 * 1024];

static constexpr int B = 8;
static constexpr int T = 2048;
static constexpr int C = 1024;

static constexpr int FPB   = 8;         // features per gemv block
static constexpr int GRID1 = C / FPB;   // 128 gemv blocks

static constexpr int ROWS_STAGE  = 8;                        // rows replicated in smem
static constexpr int STAGE_BYTES = ROWS_STAGE * C * 4;       // 32 KB (static smem ok)
static constexpr int ROWS_PER_BLOCK = 128;
static constexpr int OPS_PER_BLOCK  = ROWS_PER_BLOCK / ROWS_STAGE;  // 16 bulk ops
static constexpr int GRID2 = (B * T) / ROWS_PER_BLOCK;       // 128 blocks

// GEMV: 128 blocks (1/SM), 8 warps, warp w computes feature blockIdx.x*8+w
// for all 8 batches; x rows staged once in smem.
__global__ __launch_bounds__(256, 1)
void gemv_row1_kernel(const float* __restrict__ x,
                      const float* __restrict__ W,
                      const float* __restrict__ bias) {
    __shared__ float4 xs4[B][C / 4];   // 32 KB

    const int tid  = threadIdx.x;
    const int warp = tid >> 5;
    const int lane = tid & 31;

#pragma unroll
    for (int b = 0; b < B; b++) {
        const float4* xr = reinterpret_cast<const float4*>(x + (size_t)b * T * C + C);
        xs4[b][tid] = xr[tid];
    }
    __syncthreads();

    const int d = blockIdx.x * FPB + warp;

    const float4* w4 = reinterpret_cast<const float4*>(W + (size_t)d * C);
    float4 w[8];
#pragma unroll
    for (int i = 0; i < 8; i++) w[i] = w4[lane + 32 * i];

    float acc[B];
#pragma unroll
    for (int b = 0; b < B; b++) acc[b] = 0.0f;

#pragma unroll
    for (int i = 0; i < 8; i++) {
#pragma unroll
        for (int b = 0; b < B; b++) {
            const float4 xv = xs4[b][lane + 32 * i];
            acc[b] += w[i].x * xv.x + w[i].y * xv.y + w[i].z * xv.z + w[i].w * xv.w;
        }
    }

#pragma unroll
    for (int b = 0; b < B; b++) {
#pragma unroll
        for (int off = 16; off > 0; off >>= 1)
            acc[b] += __shfl_down_sync(0xffffffffu, acc[b], off);
    }

    if (lane == 0) {
        const float bv = bias[d];
#pragma unroll
        for (int b = 0; b < B; b++)
            g_v1[b * C + d] = acc[b] + bv;
    }
}

// Broadcast via bulk async stores (TMA path, bypasses per-thread STG).
// Block i: batch b = i>>4, rows [chunk*128, chunk*128+128) of that batch.
// Stage 8 replicated rows (32 KB) in smem, then 16 x 32 KB cp.async.bulk
// to the contiguous output range.
__global__ __launch_bounds__(256, 1)
void bulk_broadcast_kernel(float* __restrict__ out) {
    __shared__ __align__(16) float stage[ROWS_STAGE * C];   // 32 KB

    const int tid   = threadIdx.x;
    const int b     = blockIdx.x >> 4;    // 16 blocks per batch
    const int chunk = blockIdx.x & 15;

    // Fill staging: 2048 float4, 256 threads -> 8 each. v1 row is L1/L2 hot.
    const float4* v4 = reinterpret_cast<const float4*>(g_v1 + b * C);
    float4* s4 = reinterpret_cast<float4*>(stage);
#pragma unroll
    for (int i = 0; i < (ROWS_STAGE * C / 4) / 256; i++) {
        const int j = tid + 256 * i;
        s4[j] = v4[j & (C / 4 - 1)];
    }
    __syncthreads();
    asm volatile("fence.proxy.async.shared::cta;" ::: "memory");

    if (tid == 0) {
        const uint32_t saddr = (uint32_t)__cvta_generic_to_shared(stage);
        float* dst0 = out + ((size_t)b * T + (size_t)chunk * ROWS_PER_BLOCK) * C;
#pragma unroll
        for (int k = 0; k < OPS_PER_BLOCK; k++) {
            float* dst = dst0 + (size_t)k * ROWS_STAGE * C;
            asm volatile(
                "cp.async.bulk.global.shared::cta.bulk_group [%0], [%1], %2;"
                :: "l"(dst), "r"(saddr), "r"((uint32_t)STAGE_BYTES)
                : "memory");
        }
        asm volatile("cp.async.bulk.commit_group;" ::: "memory");
        asm volatile("cp.async.bulk.wait_group 0;" ::: "memory");
    }
}

extern "C" void kernel_launch(void* const* d_in, const int* in_sizes, int n_in,
                              void* d_out, int out_size) {
    const float* x    = (const float*)d_in[0];
    const float* W    = (const float*)d_in[1];
    const float* bias = (const float*)d_in[2];
    float* out = (float*)d_out;

    gemv_row1_kernel<<<GRID1, 256>>>(x, W, bias);
    bulk_broadcast_kernel<<<GRID2, 256>>>(out);
}